// round 12
// baseline (speedup 1.0000x reference)
#include <cuda_runtime.h>

// dims (4,4,32,256,256) fp32 -> BC=16 volumes of DD*HH*WW
#define DD 32
#define HH 256
#define WW 256
#define TY 2
#define NR (TY + 2)     // 4 rows (tile + y-halo)
#define ZT 16           // output planes per z-chunk (2 chunks)
#define XSEG 128        // x-width per warp (32 lanes x float4)
#define PLANE (HH * WW)

__device__ __forceinline__ float4 f4max(float4 a, float4 b) {
    return make_float4(fmaxf(a.x, b.x), fmaxf(a.y, b.y),
                       fmaxf(a.z, b.z), fmaxf(a.w, b.w));
}

__global__ __launch_bounds__(128, 5)
void nms3d_kernel(const float* __restrict__ in, float* __restrict__ out) {
    const int gw   = blockIdx.x * 4 + (threadIdx.x >> 5);  // global warp-tile id
    const int lane = threadIdx.x & 31;

    // 1b xseg | 7b ytile | 1b zchunk | 4b bc = 8192 warp tiles
    const int xs = (gw & 1) * XSEG;
    const int y0 = ((gw >> 1) & 127) * TY;
    const int z0 = ((gw >> 8) & 1) * ZT;
    const int bc = gw >> 9;
    const int x0 = xs + 4 * lane;

    const float* vol    = in  + (size_t)bc * (DD * PLANE);
    float*       ovol   = out + (size_t)bc * (DD * PLANE);
    const float* baseC  = vol + x0;
    float*       obaseC = ovol + x0;
    // one edge pointer per lane: lane31 reads the right seam, others the left
    const bool l0  = (lane == 0);
    const bool l31 = (lane == 31);
    const float* baseE  = vol + (l31 ? min(xs + XSEG, WW - 1) : max(xs - 1, 0));

    int yoff[NR];
#pragma unroll
    for (int r = 0; r < NR; ++r) {
        int y = y0 - 1 + r; y = min(max(y, 0), HH - 1);
        yoff[r] = y * WW;
    }

    // output masks: row edge * x edge
    const float mx0 = (x0 == 0) ? 0.0f : 1.0f;
    const float mx3 = (x0 + 3 == WW - 1) ? 0.0f : 1.0f;
    const float fr0 = (y0 == 0) ? 0.0f : 1.0f;
    const float fr1 = (y0 + 1 == HH - 1) ? 0.0f : 1.0f;

    float4 pA[NR], pB[NR];
    float  eA[NR], eB[NR];
    float4 VA[TY], VB[TY], MPC[TY];

    // load plane Z (z-clamped) into buffer P/E
#define PREFZ(Z, P, E)                                                        \
    do {                                                                      \
        int zz = (Z); zz = min(max(zz, 0), DD - 1);                           \
        const size_t zf = (size_t)zz * PLANE;                                 \
        _Pragma("unroll")                                                     \
        for (int r = 0; r < NR; ++r) {                                        \
            P[r] = __ldg((const float4*)(baseC + zf + yoff[r]));              \
            E[r] = __ldg(baseE + zf + yoff[r]);                               \
        }                                                                     \
    } while (0)

    // consume buffer P/E: VF[j] = 3x3 xy-window max; SZ[j] = center 8-nb max
#define RMAX(P, E, VF, SZ, DOSZ)                                              \
    do {                                                                      \
        float4 m3r[NR]; float4 m2r1, m2r2;                                    \
        _Pragma("unroll")                                                     \
        for (int r = 0; r < NR; ++r) {                                        \
            float4 w  = P[r];                                                 \
            float wm1 = __shfl_up_sync(0xffffffffu, w.w, 1);                  \
            if (l0)  wm1 = E[r];                                              \
            float w4  = __shfl_down_sync(0xffffffffu, w.x, 1);                \
            if (l31) w4 = E[r];                                               \
            float p01 = fmaxf(w.x, w.y);                                      \
            float p12 = fmaxf(w.y, w.z);                                      \
            float p23 = fmaxf(w.z, w.w);                                      \
            m3r[r] = make_float4(fmaxf(wm1, p01), fmaxf(p01, w.z),            \
                                 fmaxf(p12, w.w), fmaxf(p23, w4));            \
            if (DOSZ && r == 1)                                               \
                m2r1 = make_float4(fmaxf(wm1, w.y), fmaxf(w.x, w.z),          \
                                   fmaxf(w.y, w.w), fmaxf(w.z, w4));          \
            if (DOSZ && r == 2)                                               \
                m2r2 = make_float4(fmaxf(wm1, w.y), fmaxf(w.x, w.z),          \
                                   fmaxf(w.y, w.w), fmaxf(w.z, w4));          \
        }                                                                     \
        VF[0] = f4max(f4max(m3r[0], m3r[1]), m3r[2]);                         \
        VF[1] = f4max(f4max(m3r[1], m3r[2]), m3r[3]);                         \
        if (DOSZ) {                                                           \
            SZ[0] = f4max(f4max(m3r[0], m2r1), m3r[2]);                       \
            SZ[1] = f4max(f4max(m3r[1], m2r2), m3r[3]);                       \
        }                                                                     \
    } while (0)

    // step: emit plane ZO; buffer P holds plane ZO+1 (issued 2 steps ago);
    // refill P with plane ZO+3 if PF
#define STEP(ZO, PF, P, E, VF, VP)                                            \
    do {                                                                      \
        const size_t zoffC = (size_t)(ZO) * PLANE;                            \
        float4 c0 = __ldg((const float4*)(baseC + zoffC + yoff[1]));          \
        float4 c1 = __ldg((const float4*)(baseC + zoffC + yoff[2]));          \
        float4 szcf[TY];                                                      \
        RMAX(P, E, VF, szcf, 1);                                              \
        if (PF) PREFZ((ZO) + 3, P, E);                                        \
        if (((ZO) == 0) || ((ZO) == DD - 1)) {                                \
            float4 zq = make_float4(0.f, 0.f, 0.f, 0.f);                      \
            *(float4*)(obaseC + zoffC + yoff[1]) = zq;                        \
            *(float4*)(obaseC + zoffC + yoff[2]) = zq;                        \
        } else {                                                              \
            float4 M0 = f4max(MPC[0], VF[0]);                                 \
            float4 M1 = f4max(MPC[1], VF[1]);                                 \
            float4 o0, o1;                                                    \
            o0.x = ((c0.x > M0.x) ? c0.x : 0.0f) * fr0 * mx0;                 \
            o0.y = ((c0.y > M0.y) ? c0.y : 0.0f) * fr0;                       \
            o0.z = ((c0.z > M0.z) ? c0.z : 0.0f) * fr0;                       \
            o0.w = ((c0.w > M0.w) ? c0.w : 0.0f) * fr0 * mx3;                 \
            o1.x = ((c1.x > M1.x) ? c1.x : 0.0f) * fr1 * mx0;                 \
            o1.y = ((c1.y > M1.y) ? c1.y : 0.0f) * fr1;                       \
            o1.z = ((c1.z > M1.z) ? c1.z : 0.0f) * fr1;                       \
            o1.w = ((c1.w > M1.w) ? c1.w : 0.0f) * fr1 * mx3;                 \
            *(float4*)(obaseC + zoffC + yoff[1]) = o0;                        \
            *(float4*)(obaseC + zoffC + yoff[2]) = o1;                        \
        }                                                                     \
        MPC[0] = f4max(VP[0], szcf[0]);                                       \
        MPC[1] = f4max(VP[1], szcf[1]);                                       \
    } while (0)

    // ---- prologue: both initial planes in flight together (1 exposed latency)
    {
        float4 szc0[TY];
        PREFZ(z0 - 1, pA, eA);
        PREFZ(z0,     pB, eB);
        RMAX(pA, eA, VA, szc0, 0);     // VA = v3[z0-1]
        RMAX(pB, eB, VB, szc0, 1);     // VB = v3[z0], szc0 = szc[z0]
        MPC[0] = f4max(VA[0], szc0[0]);
        MPC[1] = f4max(VA[1], szc0[1]);
        PREFZ(z0 + 1, pA, eA);
        PREFZ(z0 + 2, pB, eB);
    }

    // ---- 16 steps as 8 ping-pong pairs; prefetch stops when the last
    //      consumed plane (z0+ZT) is already in flight
#pragma unroll 1
    for (int t = 0; t < ZT / 2; ++t) {
        const int  zo = z0 + 2 * t;
        const bool pf = (t < ZT / 2 - 1);
        STEP(zo,     pf, pA, eA, VA, VB);
        STEP(zo + 1, pf, pB, eB, VB, VA);
    }
}

extern "C" void kernel_launch(void* const* d_in, const int* in_sizes, int n_in,
                              void* d_out, int out_size) {
    const float* x = (const float*)d_in[0];
    float* out = (float*)d_out;
    (void)in_sizes; (void)n_in; (void)out_size;
    // 8192 warp-tiles / 4 warps per block
    nms3d_kernel<<<2048, 128>>>(x, out);
}

// round 14
// speedup vs baseline: 1.2673x; 1.2673x over previous
#include <cuda_runtime.h>

// dims (4,4,32,256,256) fp32 -> BC=16 volumes of DD*HH*WW
#define DD 32
#define HH 256
#define WW 256
#define TY 2
#define NR (TY + 2)     // 4 rows (tile + y-halo)
#define ZT 8            // output planes per z-chunk
#define XSEG 128        // x-width per warp (32 lanes x float4)
#define PLANE (HH * WW)

__device__ __forceinline__ float4 f4max(float4 a, float4 b) {
    return make_float4(fmaxf(a.x, b.x), fmaxf(a.y, b.y),
                       fmaxf(a.z, b.z), fmaxf(a.w, b.w));
}

__global__ __launch_bounds__(128, 5)
void nms3d_kernel(const float* __restrict__ in, float* __restrict__ out) {
    const int gw   = blockIdx.x * 4 + (threadIdx.x >> 5);  // global warp-tile id
    const int lane = threadIdx.x & 31;

    // 1b xseg | 7b ytile | 2b zchunk | 4b bc  = 16384 warp tiles
    const int xs = (gw & 1) * XSEG;
    const int y0 = ((gw >> 1) & 127) * TY;
    const int z0 = ((gw >> 8) & 3) * ZT;
    const int bc = gw >> 10;
    const int x0 = xs + 4 * lane;

    const float* vol    = in  + (size_t)bc * (DD * PLANE);
    float*       ovol   = out + (size_t)bc * (DD * PLANE);
    const float* baseC  = vol + x0;
    float*       obaseC = ovol + x0;
    // one edge pointer per lane: lane31 reads the right seam, others the left
    const bool l0  = (lane == 0);
    const bool l31 = (lane == 31);
    const float* baseE  = vol + (l31 ? min(xs + XSEG, WW - 1) : max(xs - 1, 0));

    int yoff[NR];
#pragma unroll
    for (int r = 0; r < NR; ++r) {
        int y = y0 - 1 + r; y = min(max(y, 0), HH - 1);
        yoff[r] = y * WW;
    }

    // output masks: row edge * x edge
    const float mx0 = (x0 == 0) ? 0.0f : 1.0f;
    const float mx3 = (x0 + 3 == WW - 1) ? 0.0f : 1.0f;
    const float fr0 = (y0 == 0) ? 0.0f : 1.0f;
    const float fr1 = (y0 + 1 == HH - 1) ? 0.0f : 1.0f;

    float4 pA[NR], pB[NR];
    float  eA[NR], eB[NR];
    float4 VA[TY], VB[TY], MPC[TY];
    float4 cC0, cC1;               // centers of the plane emitted this step

    // load plane Z (z-clamped) into buffer P/E
#define PREFZ(Z, P, E)                                                        \
    do {                                                                      \
        int zz = (Z); zz = min(max(zz, 0), DD - 1);                           \
        const size_t zf = (size_t)zz * PLANE;                                 \
        _Pragma("unroll")                                                     \
        for (int r = 0; r < NR; ++r) {                                        \
            P[r] = __ldg((const float4*)(baseC + zf + yoff[r]));              \
            E[r] = __ldg(baseE + zf + yoff[r]);                               \
        }                                                                     \
    } while (0)

    // consume buffer P/E: VF[j] = 3x3 xy-window max; SZ[j] = center 8-nb max
#define RMAX(P, E, VF, SZ, DOSZ)                                              \
    do {                                                                      \
        float4 m3r[NR]; float4 m2r1, m2r2;                                    \
        _Pragma("unroll")                                                     \
        for (int r = 0; r < NR; ++r) {                                        \
            float4 w  = P[r];                                                 \
            float wm1 = __shfl_up_sync(0xffffffffu, w.w, 1);                  \
            if (l0)  wm1 = E[r];                                              \
            float w4  = __shfl_down_sync(0xffffffffu, w.x, 1);                \
            if (l31) w4 = E[r];                                               \
            float p01 = fmaxf(w.x, w.y);                                      \
            float p12 = fmaxf(w.y, w.z);                                      \
            float p23 = fmaxf(w.z, w.w);                                      \
            m3r[r] = make_float4(fmaxf(wm1, p01), fmaxf(p01, w.z),            \
                                 fmaxf(p12, w.w), fmaxf(p23, w4));            \
            if (DOSZ && r == 1)                                               \
                m2r1 = make_float4(fmaxf(wm1, w.y), fmaxf(w.x, w.z),          \
                                   fmaxf(w.y, w.w), fmaxf(w.z, w4));          \
            if (DOSZ && r == 2)                                               \
                m2r2 = make_float4(fmaxf(wm1, w.y), fmaxf(w.x, w.z),          \
                                   fmaxf(w.y, w.w), fmaxf(w.z, w4));          \
        }                                                                     \
        VF[0] = f4max(f4max(m3r[0], m3r[1]), m3r[2]);                         \
        VF[1] = f4max(f4max(m3r[1], m3r[2]), m3r[3]);                         \
        if (DOSZ) {                                                           \
            SZ[0] = f4max(f4max(m3r[0], m2r1), m3r[2]);                       \
            SZ[1] = f4max(f4max(m3r[1], m2r2), m3r[3]);                       \
        }                                                                     \
    } while (0)

    // step i: emit plane zo=z0+i. Buffer P holds plane zo+1 (issued 2 steps
    // ago). Centers of plane zo were saved into cC0/cC1 last step; save
    // plane zo+1's centers before PREFZ overwrites P with plane zo+3.
#define STEP(i, P, E, VF, VP)                                                 \
    do {                                                                      \
        const int zo = z0 + (i);                                              \
        const size_t zoffC = (size_t)zo * PLANE;                              \
        float4 szcf[TY];                                                      \
        RMAX(P, E, VF, szcf, 1);                                              \
        float4 cN0 = P[1], cN1 = P[2];                                        \
        if ((i) < ZT - 2) PREFZ(z0 + (i) + 3, P, E);                          \
        if ((zo == 0) || (zo == DD - 1)) {                                    \
            float4 zq = make_float4(0.f, 0.f, 0.f, 0.f);                      \
            *(float4*)(obaseC + zoffC + yoff[1]) = zq;                        \
            *(float4*)(obaseC + zoffC + yoff[2]) = zq;                        \
        } else {                                                              \
            float4 M0 = f4max(MPC[0], VF[0]);                                 \
            float4 M1 = f4max(MPC[1], VF[1]);                                 \
            float4 o0, o1;                                                    \
            o0.x = ((cC0.x > M0.x) ? cC0.x : 0.0f) * fr0 * mx0;               \
            o0.y = ((cC0.y > M0.y) ? cC0.y : 0.0f) * fr0;                     \
            o0.z = ((cC0.z > M0.z) ? cC0.z : 0.0f) * fr0;                     \
            o0.w = ((cC0.w > M0.w) ? cC0.w : 0.0f) * fr0 * mx3;               \
            o1.x = ((cC1.x > M1.x) ? cC1.x : 0.0f) * fr1 * mx0;               \
            o1.y = ((cC1.y > M1.y) ? cC1.y : 0.0f) * fr1;                     \
            o1.z = ((cC1.z > M1.z) ? cC1.z : 0.0f) * fr1;                     \
            o1.w = ((cC1.w > M1.w) ? cC1.w : 0.0f) * fr1 * mx3;               \
            *(float4*)(obaseC + zoffC + yoff[1]) = o0;                        \
            *(float4*)(obaseC + zoffC + yoff[2]) = o1;                        \
        }                                                                     \
        cC0 = cN0; cC1 = cN1;                                                 \
        MPC[0] = f4max(VP[0], szcf[0]);                                       \
        MPC[1] = f4max(VP[1], szcf[1]);                                       \
    } while (0)

    // ---- prologue: both initial planes in flight together ----
    {
        float4 szc0[TY];
        PREFZ(z0 - 1, pA, eA);
        PREFZ(z0,     pB, eB);
        RMAX(pA, eA, VA, szc0, 0);     // VA = v3[z0-1]
        RMAX(pB, eB, VB, szc0, 1);     // VB = v3[z0], szc0 = szc[z0]
        MPC[0] = f4max(VA[0], szc0[0]);
        MPC[1] = f4max(VA[1], szc0[1]);
        cC0 = pB[1]; cC1 = pB[2];      // centers of plane z0 (step 0's emit)
        PREFZ(z0 + 1, pA, eA);
        PREFZ(z0 + 2, pB, eB);
    }

    // ---- 8 fully-unrolled steps, buffers + v3 arrays ping-pong ----
    STEP(0, pA, eA, VA, VB);
    STEP(1, pB, eB, VB, VA);
    STEP(2, pA, eA, VA, VB);
    STEP(3, pB, eB, VB, VA);
    STEP(4, pA, eA, VA, VB);
    STEP(5, pB, eB, VB, VA);
    STEP(6, pA, eA, VA, VB);
    STEP(7, pB, eB, VB, VA);
}

extern "C" void kernel_launch(void* const* d_in, const int* in_sizes, int n_in,
                              void* d_out, int out_size) {
    const float* x = (const float*)d_in[0];
    float* out = (float*)d_out;
    (void)in_sizes; (void)n_in; (void)out_size;
    // 16384 warp-tiles / 4 warps per block
    nms3d_kernel<<<4096, 128>>>(x, out);
}